// round 3
// baseline (speedup 1.0000x reference)
#include <cuda_runtime.h>
#include <cuda_bf16.h>
#include <math.h>

// Problem constants
#define NB 4          // batch
#define SS 2048       // seq len
#define HID 1024
#define NH 16         // heads
#define NKV 4
#define DD 64
#define NA 2          // two attentions

// ---------------- scratch (device globals; no allocation allowed) ------------
__device__ float g_Q  [NA*NB*SS*NH*DD];   // (a,b,s, h*64+d)   64 MB
__device__ float g_K  [NA*NB*SS*NKV*DD];  // (a,b,s, kv*64+d)  16 MB
__device__ float g_U  [NA*NB*SS*NH];      // (a,b,s,h)
__device__ float g_UT [NA*NB*NH*SS];      // (a,b,h,s)
__device__ float g_WVO[NA*HID*NH];        // (a,hid,h)
__device__ float g_SH [NA*NB*NH*SS];      // per-head scalar attention out
__device__ float g_SIG[NA*NB*SS];         // sigmoid(s) per attn
__device__ int   g_sizes[NB];

// ---------------- fast exp (FFMA-only, no MUFU) ------------------------------
__device__ __forceinline__ float fexp(float x) {
    x = fmaxf(x, -87.0f);                       // inputs are always <= 0 here
    float y = x * 1.4426950408889634f;          // x * log2(e)
    float t = y + 12582912.0f;                  // 1.5*2^23 round-to-int magic
    int   n = __float_as_int(t) - 0x4B400000;   // rounded integer part
    float f = y - (t - 12582912.0f);            // frac in [-0.5, 0.5]
    // 2^f Taylor, degree 6 (rel err ~1e-7)
    float p = 1.5403530e-4f;
    p = fmaf(p, f, 1.3333558e-3f);
    p = fmaf(p, f, 9.6181291e-3f);
    p = fmaf(p, f, 5.5504109e-2f);
    p = fmaf(p, f, 2.4022651e-1f);
    p = fmaf(p, f, 6.9314718e-1f);
    p = fmaf(p, f, 1.0f);
    return p * __int_as_float((n + 127) << 23);
}

// ---------------- wvo precompute: WVO[a][hid][h] = sum_d Wv[hid,kv*64+d]*Wo[h*64+d]
__global__ void wvo_kernel(const float* __restrict__ Wv1, const float* __restrict__ Wo1,
                           const float* __restrict__ Wv2, const float* __restrict__ Wo2) {
    int idx = blockIdx.x * blockDim.x + threadIdx.x;   // NA*HID*NH = 32768
    if (idx >= NA * HID * NH) return;
    int h   = idx & 15;
    int hid = (idx >> 4) & 1023;
    int a   = idx >> 14;
    const float* Wv = a ? Wv2 : Wv1;
    const float* Wo = a ? Wo2 : Wo1;
    int kv = h >> 2;
    float s = 0.f;
    const float* vr = Wv + (size_t)hid * (NKV * DD) + kv * DD;
    const float* wr = Wo + h * DD;
#pragma unroll
    for (int d = 0; d < DD; d++) s = fmaf(vr[d], wr[d], s);
    g_WVO[(size_t)a * HID * NH + hid * NH + h] = s;
}

// ---------------- SGEMM: C(MxN) = A(MxK) * B(KxN), row-major, 128x128x8 ------
__global__ __launch_bounds__(256) void sgemm(const float* __restrict__ A,
                                             const float* __restrict__ B,
                                             float* __restrict__ C,
                                             int M, int N, int K) {
    __shared__ __align__(16) float As[8][128];
    __shared__ __align__(16) float Bs[8][128];
    int tid = threadIdx.x;
    int bm = blockIdx.y * 128;
    int bn = blockIdx.x * 128;
    int ty = tid >> 4, tx = tid & 15;

    int arow = tid >> 1;        // 0..127
    int acol = (tid & 1) * 4;   // 0 or 4
    int brow = tid >> 5;        // 0..7
    int bcol = (tid & 31) * 4;  // 0..124

    float acc[8][8];
#pragma unroll
    for (int i = 0; i < 8; i++)
#pragma unroll
        for (int j = 0; j < 8; j++) acc[i][j] = 0.f;

    const float* Aptr = A + (size_t)(bm + arow) * K + acol;

    for (int k0 = 0; k0 < K; k0 += 8) {
        float4 av = *(const float4*)(Aptr + k0);
        As[acol + 0][arow] = av.x;
        As[acol + 1][arow] = av.y;
        As[acol + 2][arow] = av.z;
        As[acol + 3][arow] = av.w;

        int gn = bn + bcol;
        const float* Bp = B + (size_t)(k0 + brow) * N + gn;
        if (gn + 3 < N) {
            *(float4*)&Bs[brow][bcol] = *(const float4*)Bp;
        } else {
#pragma unroll
            for (int j = 0; j < 4; j++)
                Bs[brow][bcol + j] = (gn + j < N) ? Bp[j] : 0.f;
        }
        __syncthreads();

#pragma unroll
        for (int kk = 0; kk < 8; kk++) {
            float4 a0 = *(const float4*)&As[kk][ty * 4];
            float4 a1 = *(const float4*)&As[kk][64 + ty * 4];
            float4 b0 = *(const float4*)&Bs[kk][tx * 4];
            float4 b1 = *(const float4*)&Bs[kk][64 + tx * 4];
            float ar[8] = {a0.x, a0.y, a0.z, a0.w, a1.x, a1.y, a1.z, a1.w};
            float br[8] = {b0.x, b0.y, b0.z, b0.w, b1.x, b1.y, b1.z, b1.w};
#pragma unroll
            for (int i = 0; i < 8; i++)
#pragma unroll
                for (int j = 0; j < 8; j++) acc[i][j] = fmaf(ar[i], br[j], acc[i][j]);
        }
        __syncthreads();
    }
#pragma unroll
    for (int i = 0; i < 8; i++) {
        int row = bm + ((i < 4) ? (ty * 4 + i) : (64 + ty * 4 + i - 4));
#pragma unroll
        for (int j = 0; j < 8; j++) {
            int col = bn + ((j < 4) ? (tx * 4 + j) : (64 + tx * 4 + j - 4));
            if (col < N) C[(size_t)row * N + col] = acc[i][j];
        }
    }
}

// ---------------- U transpose: (a,b,s,h) -> (a,b,h,s) ------------------------
__global__ void ut_kernel() {
    int idx = blockIdx.x * blockDim.x + threadIdx.x;   // NA*NB*SS*NH = 262144
    if (idx >= NA * NB * SS * NH) return;
    int h  = idx & 15;
    int s  = (idx >> 4) & (SS - 1);
    int ab = idx >> 15;
    g_UT[((size_t)ab * NH + h) * SS + s] = g_U[idx];
}

// ---------------- attention with scalar values (flash-style) -----------------
// grid: (SS/64, NA*NB*NH), 256 threads
__global__ __launch_bounds__(256) void attn_kernel() {
    __shared__ __align__(16) float Qs[64][64];
    __shared__ __align__(16) float Ks[64][64];
    __shared__ __align__(16) float Ss[64][64];

    int tid = threadIdx.x;
    int abh = blockIdx.y;               // = (a*NB + b)*NH + h
    int h = abh & 15;
    int ab = abh >> 4;                  // a*NB + b
    int q0 = blockIdx.x * 64;

    const float* Qg = g_Q + (size_t)ab * SS * (NH * DD);
    const float* Kg = g_K + (size_t)ab * SS * (NKV * DD);
    const float* UT = g_UT + (size_t)abh * SS;

    // load Q tile, transposed + scaled by 1/sqrt(64)
    {
        int q = tid >> 2, g4 = tid & 3;
        const float* src = Qg + (size_t)(q0 + q) * (NH * DD) + h * DD + g4 * 16;
#pragma unroll
        for (int j = 0; j < 4; j++) {
            float4 v = ((const float4*)src)[j];
            int d = g4 * 16 + j * 4;
            Qs[d + 0][q] = v.x * 0.125f;
            Qs[d + 1][q] = v.y * 0.125f;
            Qs[d + 2][q] = v.z * 0.125f;
            Qs[d + 3][q] = v.w * 0.125f;
        }
    }

    float m_run = -1e30f, l_run = 0.f, o_run = 0.f;
    int r = tid >> 2, g = tid & 3;      // softmax phase mapping
    int ty = tid >> 4, tx = tid & 15;   // score phase mapping
    int kvoff = (h >> 2) * DD;

    for (int kt = 0; kt < SS / 64; kt++) {
        // load K tile transposed
        {
            int kk = tid >> 2, g4 = tid & 3;
            const float* src = Kg + (size_t)(kt * 64 + kk) * (NKV * DD) + kvoff + g4 * 16;
#pragma unroll
            for (int j = 0; j < 4; j++) {
                float4 v = ((const float4*)src)[j];
                int d = g4 * 16 + j * 4;
                Ks[d + 0][kk] = v.x;
                Ks[d + 1][kk] = v.y;
                Ks[d + 2][kk] = v.z;
                Ks[d + 3][kk] = v.w;
            }
        }
        __syncthreads();

        // scores: 64x64 tile, each thread 4x4
        float acc[4][4];
#pragma unroll
        for (int i = 0; i < 4; i++)
#pragma unroll
            for (int j = 0; j < 4; j++) acc[i][j] = 0.f;
#pragma unroll 16
        for (int d = 0; d < 64; d++) {
            float4 av = *(const float4*)&Qs[d][ty * 4];
            float4 bv = *(const float4*)&Ks[d][tx * 4];
            float ar[4] = {av.x, av.y, av.z, av.w};
            float br[4] = {bv.x, bv.y, bv.z, bv.w};
#pragma unroll
            for (int i = 0; i < 4; i++)
#pragma unroll
                for (int j = 0; j < 4; j++) acc[i][j] = fmaf(ar[i], br[j], acc[i][j]);
        }
#pragma unroll
        for (int i = 0; i < 4; i++) {
            float4 v = make_float4(acc[i][0], acc[i][1], acc[i][2], acc[i][3]);
            *(float4*)&Ss[ty * 4 + i][tx * 4] = v;
        }
        __syncthreads();

        // online softmax: thread (r, g) handles row r, keys g*16..g*16+15
        int base = g * 16;
        float4 s0 = *(const float4*)&Ss[r][base + 0];
        float4 s1 = *(const float4*)&Ss[r][base + 4];
        float4 s2 = *(const float4*)&Ss[r][base + 8];
        float4 s3 = *(const float4*)&Ss[r][base + 12];

        float lm = fmaxf(fmaxf(fmaxf(s0.x, s0.y), fmaxf(s0.z, s0.w)),
                         fmaxf(fmaxf(s1.x, s1.y), fmaxf(s1.z, s1.w)));
        lm = fmaxf(lm, fmaxf(fmaxf(fmaxf(s2.x, s2.y), fmaxf(s2.z, s2.w)),
                             fmaxf(fmaxf(s3.x, s3.y), fmaxf(s3.z, s3.w))));
        lm = fmaxf(lm, __shfl_xor_sync(0xffffffffu, lm, 1));
        lm = fmaxf(lm, __shfl_xor_sync(0xffffffffu, lm, 2));

        float m_new = fmaxf(m_run, lm);
        float corr = fexp(m_run - m_new);

        const float* up = UT + kt * 64 + base;
        float4 u0 = *(const float4*)(up + 0);
        float4 u1 = *(const float4*)(up + 4);
        float4 u2 = *(const float4*)(up + 8);
        float4 u3 = *(const float4*)(up + 12);

        float ls = 0.f, la = 0.f, e;
        e = fexp(s0.x - m_new); ls += e; la = fmaf(e, u0.x, la);
        e = fexp(s0.y - m_new); ls += e; la = fmaf(e, u0.y, la);
        e = fexp(s0.z - m_new); ls += e; la = fmaf(e, u0.z, la);
        e = fexp(s0.w - m_new); ls += e; la = fmaf(e, u0.w, la);
        e = fexp(s1.x - m_new); ls += e; la = fmaf(e, u1.x, la);
        e = fexp(s1.y - m_new); ls += e; la = fmaf(e, u1.y, la);
        e = fexp(s1.z - m_new); ls += e; la = fmaf(e, u1.z, la);
        e = fexp(s1.w - m_new); ls += e; la = fmaf(e, u1.w, la);
        e = fexp(s2.x - m_new); ls += e; la = fmaf(e, u2.x, la);
        e = fexp(s2.y - m_new); ls += e; la = fmaf(e, u2.y, la);
        e = fexp(s2.z - m_new); ls += e; la = fmaf(e, u2.z, la);
        e = fexp(s2.w - m_new); ls += e; la = fmaf(e, u2.w, la);
        e = fexp(s3.x - m_new); ls += e; la = fmaf(e, u3.x, la);
        e = fexp(s3.y - m_new); ls += e; la = fmaf(e, u3.y, la);
        e = fexp(s3.z - m_new); ls += e; la = fmaf(e, u3.z, la);
        e = fexp(s3.w - m_new); ls += e; la = fmaf(e, u3.w, la);

        ls += __shfl_xor_sync(0xffffffffu, ls, 1);
        la += __shfl_xor_sync(0xffffffffu, la, 1);
        ls += __shfl_xor_sync(0xffffffffu, ls, 2);
        la += __shfl_xor_sync(0xffffffffu, la, 2);

        l_run = fmaf(l_run, corr, ls);
        o_run = fmaf(o_run, corr, la);
        m_run = m_new;
    }

    if (g == 0)
        g_SH[(size_t)abh * SS + q0 + r] = o_run / l_run;
}

// ---------------- combine heads + sigmoid ------------------------------------
__global__ void combine_kernel() {
    int idx = blockIdx.x * blockDim.x + threadIdx.x;   // NA*NB*SS = 16384
    if (idx >= NA * NB * SS) return;
    int q = idx & (SS - 1);
    int ab = idx >> 11;
    float s = 0.f;
#pragma unroll
    for (int h = 0; h < NH; h++) s += g_SH[((size_t)ab * NH + h) * SS + q];
    g_SIG[idx] = 1.0f / (1.0f + expf(-s));
}

// ---------------- sizes (fp64 mean, fp32 final formula, C truncation) --------
__global__ void sizes_kernel(const float* __restrict__ scale_p) {
    int b = blockIdx.x;
    int tid = threadIdx.x;
    __shared__ double red[256];
    double s = 0.0;
    for (int q = tid; q < SS; q += 256) s += (double)g_SIG[b * SS + q];
    red[tid] = s;
    __syncthreads();
    for (int st = 128; st > 0; st >>= 1) {
        if (tid < st) red[tid] += red[tid + st];
        __syncthreads();
    }
    if (tid == 0) {
        float mean = (float)(red[0] / (double)SS);
        float val = mean * scale_p[0] * 8160.0f + 32.0f;   // (MAX-MIN)=8160, MIN=32
        g_sizes[b] = (int)val;                              // trunc toward zero
    }
}

// ---------------- segment weighted pooling + output --------------------------
// grid: (max_len, NB), 256 threads. out layout: [pooled f32 | mask f32 | sizes f32]
__global__ __launch_bounds__(256) void pool_kernel(const float* __restrict__ x,
                                                   float* __restrict__ out,
                                                   int ml, int extras) {
    int b = blockIdx.y, j = blockIdx.x, tid = threadIdx.x;
    int sz = g_sizes[b];
    int off = ml - sz;
    float* orow = out + ((size_t)(b * ml + j)) * HID;
    int c = tid * 4;
    size_t maskbase = (size_t)NB * ml * HID;

    if (j < off) {
        *(float4*)&orow[c] = make_float4(0.f, 0.f, 0.f, 0.f);
        if (extras && tid == 0) out[maskbase + (size_t)b * ml + j] = 0.0f;
    } else {
        int s = j - off;
        // replicate np.linspace(0, S, sz+1) boundaries bit-exactly (fp64)
        double step = 2048.0 / (double)sz;
        int lo = (s == 0) ? 0 : (int)floor((double)s * step);
        int hi = (s + 1 == sz) ? SS : (int)floor((double)(s + 1) * step);
        float4 acc = make_float4(0.f, 0.f, 0.f, 0.f);
        float wsum = 0.f;
        const float* wv = g_SIG + (NA - 1) * NB * SS + b * SS;  // attn-2 sigmoid
        const float* xb = x + (size_t)b * SS * HID;
        for (int t = lo; t < hi; t++) {
            float w = wv[t];
            float4 xv = *(const float4*)&xb[(size_t)t * HID + c];
            acc.x = fmaf(xv.x, w, acc.x);
            acc.y = fmaf(xv.y, w, acc.y);
            acc.z = fmaf(xv.z, w, acc.z);
            acc.w = fmaf(xv.w, w, acc.w);
            wsum += w;
        }
        float den = wsum + 1e-8f;
        *(float4*)&orow[c] = make_float4(acc.x / den, acc.y / den, acc.z / den, acc.w / den);
        if (extras && tid == 0) out[maskbase + (size_t)b * ml + j] = 1.0f;
    }
    if (extras && j == 0 && tid == 0)
        out[maskbase + (size_t)NB * ml + b] = (float)sz;
}

// ---------------- host ---------------------------------------------------------
extern "C" void kernel_launch(void* const* d_in, const int* in_sizes, int n_in,
                              void* d_out, int out_size) {
    const float* x    = (const float*)d_in[0];
    const float* Wq1  = (const float*)d_in[1];
    const float* Wk1  = (const float*)d_in[2];
    const float* Wv1  = (const float*)d_in[3];
    const float* Wo1  = (const float*)d_in[4];
    const float* Wq2  = (const float*)d_in[5];
    const float* Wk2  = (const float*)d_in[6];
    const float* Wv2  = (const float*)d_in[7];
    const float* Wo2  = (const float*)d_in[8];
    const float* scl  = (const float*)d_in[9];
    float* out = (float*)d_out;

    float *Qp, *Kp, *Up, *WVOp;
    cudaGetSymbolAddress((void**)&Qp, g_Q);
    cudaGetSymbolAddress((void**)&Kp, g_K);
    cudaGetSymbolAddress((void**)&Up, g_U);
    cudaGetSymbolAddress((void**)&WVOp, g_WVO);

    // derive max_len from out_size: out = B*ml*(HID+1) + B floats
    long long osz = (long long)out_size;
    int ml, extras;
    if (osz > NB && ((osz - NB) % (long long)(NB * (HID + 1))) == 0) {
        ml = (int)((osz - NB) / (NB * (HID + 1)));
        extras = 1;
    } else {
        ml = (int)(osz / (NB * HID));
        extras = 0;
    }
    if (ml < 1) ml = 1;

    const int M = NB * SS;  // 8192

    wvo_kernel<<<(NA * HID * NH + 255) / 256, 256>>>(Wv1, Wo1, Wv2, Wo2);

    sgemm<<<dim3(8, M / 128), 256>>>(x, Wq1, Qp, M, NH * DD, HID);
    sgemm<<<dim3(8, M / 128), 256>>>(x, Wq2, Qp + (size_t)M * NH * DD, M, NH * DD, HID);
    sgemm<<<dim3(2, M / 128), 256>>>(x, Wk1, Kp, M, NKV * DD, HID);
    sgemm<<<dim3(2, M / 128), 256>>>(x, Wk2, Kp + (size_t)M * NKV * DD, M, NKV * DD, HID);
    sgemm<<<dim3(1, M / 128), 256>>>(x, WVOp, Up, M, NH, HID);
    sgemm<<<dim3(1, M / 128), 256>>>(x, WVOp + HID * NH, Up + (size_t)M * NH, M, NH, HID);

    ut_kernel<<<(NA * NB * SS * NH + 255) / 256, 256>>>();

    attn_kernel<<<dim3(SS / 64, NA * NB * NH), 256>>>();

    combine_kernel<<<(NA * NB * SS + 255) / 256, 256>>>();
    sizes_kernel<<<NB, 256>>>(scl);

    pool_kernel<<<dim3(ml, NB), 256>>>(x, out, ml, extras);
}

// round 4
// speedup vs baseline: 1.2218x; 1.2218x over previous
#include <cuda_runtime.h>
#include <cuda_bf16.h>
#include <math.h>

// Problem constants
#define NB 4          // batch
#define SS 2048       // seq len
#define HID 1024
#define NH 16         // heads
#define NKV 4
#define DD 64
#define NA 2          // two attentions
#define NTOT 2592     // 1024(Q1)+1024(Q2)+256(K1)+256(K2)+16(U1)+16(U2)

typedef unsigned long long ull;

// ---------------- scratch (device globals; no allocation allowed) ------------
__device__ float g_Bcat[HID * NTOT];        // concatenated weights [K][NTOT]
__device__ float g_C   [NB * SS * NTOT];    // fused projection output  ~85 MB
__device__ float g_UT  [NA * NB * NH * SS]; // scalar-values transposed (a,b,h,s)
__device__ float g_SH  [NA * NB * NH * SS]; // per-head scalar attention out
__device__ float g_SIG [NA * NB * SS];      // sigmoid(score) per attn
__device__ int   g_sizes[NB];

// ---------------- f32x2 packed helpers ---------------------------------------
__device__ __forceinline__ ull pk(float lo, float hi) {
    ull r; asm("mov.b64 %0, {%1, %2};" : "=l"(r) : "f"(lo), "f"(hi)); return r;
}
__device__ __forceinline__ float2 upk(ull v) {
    float2 r; asm("mov.b64 {%0, %1}, %2;" : "=f"(r.x), "=f"(r.y) : "l"(v)); return r;
}
__device__ __forceinline__ void upki(ull v, int& a, int& b) {
    asm("mov.b64 {%0, %1}, %2;" : "=r"(a), "=r"(b) : "l"(v));
}
__device__ __forceinline__ ull pki(int lo, int hi) {
    ull r; asm("mov.b64 %0, {%1, %2};" : "=l"(r) : "r"(lo), "r"(hi)); return r;
}
#define FMA2(d, a, b, c) asm("fma.rn.f32x2 %0, %1, %2, %3;" : "=l"(d) : "l"(a), "l"(b), "l"(c))
#define MUL2(d, a, b)    asm("mul.rn.f32x2 %0, %1, %2;"     : "=l"(d) : "l"(a), "l"(b))
#define ADD2(d, a, b)    asm("add.rn.f32x2 %0, %1, %2;"     : "=l"(d) : "l"(a), "l"(b))

// ---------------- scalar fast exp (FFMA-only, clamped) -----------------------
__device__ __forceinline__ float fexp(float x) {
    x = fmaxf(x, -87.0f);
    float y = x * 1.4426950408889634f;
    float t = y + 12582912.0f;
    int   n = __float_as_int(t) - 0x4B400000;
    float f = y - (t - 12582912.0f);
    float p = 1.3333558e-3f;
    p = fmaf(p, f, 9.6181291e-3f);
    p = fmaf(p, f, 5.5504109e-2f);
    p = fmaf(p, f, 2.4022651e-1f);
    p = fmaf(p, f, 6.9314718e-1f);
    p = fmaf(p, f, 1.0f);
    return p * __int_as_float((n + 127) << 23);
}

// ---------------- weight packing: Bcat[k][c] ---------------------------------
__global__ void pack_weights(const float* __restrict__ Wq1, const float* __restrict__ Wk1,
                             const float* __restrict__ Wv1, const float* __restrict__ Wo1,
                             const float* __restrict__ Wq2, const float* __restrict__ Wk2,
                             const float* __restrict__ Wv2, const float* __restrict__ Wo2) {
    int c = blockIdx.x * 256 + threadIdx.x;
    int k = blockIdx.y;
    if (c >= NTOT) return;
    float v;
    if (c < 1024)      v = Wq1[(size_t)k * 1024 + c];
    else if (c < 2048) v = Wq2[(size_t)k * 1024 + (c - 1024)];
    else if (c < 2304) v = Wk1[(size_t)k * 256 + (c - 2048)];
    else if (c < 2560) v = Wk2[(size_t)k * 256 + (c - 2304)];
    else {
        int cc = c - 2560; int a = cc >> 4, h = cc & 15;
        const float* Wv = a ? Wv2 : Wv1;
        const float* Wo = a ? Wo2 : Wo1;
        int kv = h >> 2;
        float s = 0.f;
        const float* vr = Wv + (size_t)k * (NKV * DD) + kv * DD;
        const float* wr = Wo + h * DD;
#pragma unroll
        for (int d = 0; d < DD; d++) s = fmaf(vr[d], wr[d], s);
        v = s;
    }
    g_Bcat[(size_t)k * NTOT + c] = v;
}

// ---------------- fused projection GEMM: C = x @ Bcat, 128x128x8, f32x2 ------
__global__ __launch_bounds__(256, 2) void gemm_fused(const float* __restrict__ A) {
    __shared__ __align__(16) float As[8][128];
    __shared__ __align__(16) float Bs[8][128];
    const int N = NTOT, K = HID;
    int tid = threadIdx.x;
    int bm = blockIdx.y * 128;
    int bn = blockIdx.x * 128;
    int ty = tid >> 4, tx = tid & 15;

    int arow = tid >> 1, acol = (tid & 1) * 4;
    int brow = tid >> 5, bcol = (tid & 31) * 4;
    int gn = bn + bcol;
    bool edge = (bn + 128 > N);

    ull acc2[8][4];
#pragma unroll
    for (int i = 0; i < 8; i++)
#pragma unroll
        for (int j = 0; j < 4; j++) acc2[i][j] = 0ull;

    const float* Aptr = A + (size_t)(bm + arow) * K + acol;
    const float* Bptr = g_Bcat + (size_t)brow * N + gn;

    float4 apre, bpre;
    apre = *(const float4*)(Aptr);
    if (!edge) bpre = *(const float4*)(Bptr);
    else {
        bpre.x = (gn + 0 < N) ? Bptr[0] : 0.f;
        bpre.y = (gn + 1 < N) ? Bptr[1] : 0.f;
        bpre.z = (gn + 2 < N) ? Bptr[2] : 0.f;
        bpre.w = (gn + 3 < N) ? Bptr[3] : 0.f;
    }

    for (int k0 = 0; k0 < K; k0 += 8) {
        As[acol + 0][arow] = apre.x;
        As[acol + 1][arow] = apre.y;
        As[acol + 2][arow] = apre.z;
        As[acol + 3][arow] = apre.w;
        *(float4*)&Bs[brow][bcol] = bpre;
        __syncthreads();

        if (k0 + 8 < K) {
            apre = *(const float4*)(Aptr + k0 + 8);
            const float* Bp = Bptr + (size_t)(k0 + 8) * N;
            if (!edge) bpre = *(const float4*)Bp;
            else {
                bpre.x = (gn + 0 < N) ? Bp[0] : 0.f;
                bpre.y = (gn + 1 < N) ? Bp[1] : 0.f;
                bpre.z = (gn + 2 < N) ? Bp[2] : 0.f;
                bpre.w = (gn + 3 < N) ? Bp[3] : 0.f;
            }
        }

#pragma unroll
        for (int kk = 0; kk < 8; kk++) {
            float4 a0 = *(const float4*)&As[kk][ty * 4];
            float4 a1 = *(const float4*)&As[kk][64 + ty * 4];
            ulonglong2 b0 = *(const ulonglong2*)&Bs[kk][tx * 4];
            ulonglong2 b1 = *(const ulonglong2*)&Bs[kk][64 + tx * 4];
            ull ap[8];
            ap[0] = pk(a0.x, a0.x); ap[1] = pk(a0.y, a0.y);
            ap[2] = pk(a0.z, a0.z); ap[3] = pk(a0.w, a0.w);
            ap[4] = pk(a1.x, a1.x); ap[5] = pk(a1.y, a1.y);
            ap[6] = pk(a1.z, a1.z); ap[7] = pk(a1.w, a1.w);
            ull bp[4] = {b0.x, b0.y, b1.x, b1.y};
#pragma unroll
            for (int i = 0; i < 8; i++)
#pragma unroll
                for (int j = 0; j < 4; j++) FMA2(acc2[i][j], ap[i], bp[j], acc2[i][j]);
        }
        __syncthreads();
    }

#pragma unroll
    for (int i = 0; i < 8; i++) {
        int row = bm + ((i < 4) ? (ty * 4 + i) : (64 + ty * 4 + i - 4));
#pragma unroll
        for (int j = 0; j < 4; j++) {
            int col = bn + ((j < 2) ? (tx * 4 + j * 2) : (64 + tx * 4 + (j - 2) * 2));
            if (col < N) {
                float2 v = upk(acc2[i][j]);
                *(float2*)&g_C[(size_t)row * N + col] = v;
            }
        }
    }
}

// ---------------- U transpose: C cols -> (a,b,h,s) ---------------------------
__global__ void ut_kernel() {
    int o = blockIdx.x * blockDim.x + threadIdx.x;   // NA*NB*NH*SS = 262144
    if (o >= NA * NB * NH * SS) return;
    int s = o & (SS - 1);
    int abh = o >> 11;
    int h = abh & 15, ab = abh >> 4;
    int a = ab >> 2, b = ab & 3;
    g_UT[o] = g_C[(size_t)(b * SS + s) * NTOT + 2560 + a * 16 + h];
}

// ---------------- attention with scalar values (flash-style, f32x2) ----------
// grid: (SS/64, NA*NB*NH), 256 threads
__global__ __launch_bounds__(256) void attn_kernel() {
    __shared__ __align__(16) float Qs[64][64];
    __shared__ __align__(16) float Ks[64][64];
    __shared__ __align__(16) float Ss[64][64];

    int tid = threadIdx.x;
    int abh = blockIdx.y;               // (a*NB + b)*NH + h
    int h = abh & 15;
    int ab = abh >> 4;
    int a = ab >> 2, b = ab & 3;
    int q0 = blockIdx.x * 64;

    int qcol = a * 1024 + h * DD;
    int kcol = 2048 + a * 256 + (h >> 2) * DD;
    const float* Cb = g_C + (size_t)b * SS * NTOT;
    const float* UT = g_UT + (size_t)abh * SS;

    // load Q tile, transposed + scaled by 1/sqrt(64)
    {
        int q = tid >> 2, g4 = tid & 3;
        const float* src = Cb + (size_t)(q0 + q) * NTOT + qcol + g4 * 16;
#pragma unroll
        for (int j = 0; j < 4; j++) {
            float4 v = ((const float4*)src)[j];
            int d = g4 * 16 + j * 4;
            Qs[d + 0][q] = v.x * 0.125f;
            Qs[d + 1][q] = v.y * 0.125f;
            Qs[d + 2][q] = v.z * 0.125f;
            Qs[d + 3][q] = v.w * 0.125f;
        }
    }

    // packed-exp constants (registers)
    const ull C_L2E  = pk(1.4426950408889634f, 1.4426950408889634f);
    const ull C_MAG  = pk(12582912.0f, 12582912.0f);
    const ull C_NMAG = pk(-12582912.0f, -12582912.0f);
    const ull C_N1   = pk(-1.0f, -1.0f);
    const ull P5 = pk(1.3333558e-3f, 1.3333558e-3f);
    const ull P4 = pk(9.6181291e-3f, 9.6181291e-3f);
    const ull P3 = pk(5.5504109e-2f, 5.5504109e-2f);
    const ull P2 = pk(2.4022651e-1f, 2.4022651e-1f);
    const ull P1 = pk(6.9314718e-1f, 6.9314718e-1f);
    const ull P0 = pk(1.0f, 1.0f);

    float m_run = -1e30f, l_run = 0.f, o_run = 0.f;
    int r = tid >> 2, g = tid & 3;      // softmax mapping
    int ty = tid >> 4, tx = tid & 15;   // score mapping
    int kk = tid >> 2, g4 = tid & 3;    // K-load mapping

    // prefetch K tile 0
    float4 pre[4];
    {
        const float* src = Cb + (size_t)(0 * 64 + kk) * NTOT + kcol + g4 * 16;
#pragma unroll
        for (int j = 0; j < 4; j++) pre[j] = ((const float4*)src)[j];
    }

    for (int kt = 0; kt < SS / 64; kt++) {
        // store prefetched K tile (transposed)
#pragma unroll
        for (int j = 0; j < 4; j++) {
            int d = g4 * 16 + j * 4;
            Ks[d + 0][kk] = pre[j].x;
            Ks[d + 1][kk] = pre[j].y;
            Ks[d + 2][kk] = pre[j].z;
            Ks[d + 3][kk] = pre[j].w;
        }
        __syncthreads();

        // prefetch next K tile while computing
        if (kt + 1 < SS / 64) {
            const float* src = Cb + (size_t)((kt + 1) * 64 + kk) * NTOT + kcol + g4 * 16;
#pragma unroll
            for (int j = 0; j < 4; j++) pre[j] = ((const float4*)src)[j];
        }

        // scores: 64x64 tile, each thread 4 rows x 4 cols (2 packed pairs)
        ull acc2[4][2];
#pragma unroll
        for (int i = 0; i < 4; i++) { acc2[i][0] = 0ull; acc2[i][1] = 0ull; }
#pragma unroll 16
        for (int d = 0; d < 64; d++) {
            float4 av = *(const float4*)&Qs[d][ty * 4];
            ulonglong2 bv = *(const ulonglong2*)&Ks[d][tx * 4];
            ull a0 = pk(av.x, av.x), a1 = pk(av.y, av.y);
            ull a2 = pk(av.z, av.z), a3 = pk(av.w, av.w);
            FMA2(acc2[0][0], a0, bv.x, acc2[0][0]); FMA2(acc2[0][1], a0, bv.y, acc2[0][1]);
            FMA2(acc2[1][0], a1, bv.x, acc2[1][0]); FMA2(acc2[1][1], a1, bv.y, acc2[1][1]);
            FMA2(acc2[2][0], a2, bv.x, acc2[2][0]); FMA2(acc2[2][1], a2, bv.y, acc2[2][1]);
            FMA2(acc2[3][0], a3, bv.x, acc2[3][0]); FMA2(acc2[3][1], a3, bv.y, acc2[3][1]);
        }
#pragma unroll
        for (int i = 0; i < 4; i++) {
            float2 v0 = upk(acc2[i][0]);
            float2 v1 = upk(acc2[i][1]);
            *(float4*)&Ss[ty * 4 + i][tx * 4] = make_float4(v0.x, v0.y, v1.x, v1.y);
        }
        __syncthreads();

        // online softmax: thread (r,g) handles row r, keys g*16..g*16+15
        int base = g * 16;
        const ulonglong2* srow = (const ulonglong2*)&Ss[r][base];
        ulonglong2 sp0 = srow[0], sp1 = srow[1];
        // row max (scores are O(1); no clamp needed in packed exp)
        float2 f0 = upk(sp0.x), f1 = upk(sp0.y), f2 = upk(sp1.x), f3 = upk(sp1.y);
        ulonglong2 sp2 = ((const ulonglong2*)&Ss[r][base])[2];
        ulonglong2 sp3 = ((const ulonglong2*)&Ss[r][base])[3];
        float2 f4 = upk(sp2.x), f5 = upk(sp2.y), f6 = upk(sp3.x), f7 = upk(sp3.y);
        float lm = fmaxf(fmaxf(fmaxf(f0.x, f0.y), fmaxf(f1.x, f1.y)),
                         fmaxf(fmaxf(f2.x, f2.y), fmaxf(f3.x, f3.y)));
        lm = fmaxf(lm, fmaxf(fmaxf(fmaxf(f4.x, f4.y), fmaxf(f5.x, f5.y)),
                             fmaxf(fmaxf(f6.x, f6.y), fmaxf(f7.x, f7.y))));
        lm = fmaxf(lm, __shfl_xor_sync(0xffffffffu, lm, 1));
        lm = fmaxf(lm, __shfl_xor_sync(0xffffffffu, lm, 2));

        float m_new = fmaxf(m_run, lm);
        float corr = fexp(m_run - m_new);
        ull mneg2 = pk(-m_new, -m_new);

        const ulonglong2* up = (const ulonglong2*)(UT + kt * 64 + base);
        ulonglong2 u01 = up[0], u23 = up[1], u45 = up[2], u67 = up[3];

        ull ls2 = 0ull, la2 = 0ull;
        ull spair[8] = {sp0.x, sp0.y, sp1.x, sp1.y, sp2.x, sp2.y, sp3.x, sp3.y};
        ull upair[8] = {u01.x, u01.y, u23.x, u23.y, u45.x, u45.y, u67.x, u67.y};
#pragma unroll
        for (int p = 0; p < 8; p++) {
            ull x2; ADD2(x2, spair[p], mneg2);      // s - m_new (both <= 0, > -90)
            ull y2; MUL2(y2, x2, C_L2E);
            ull t2; ADD2(t2, y2, C_MAG);
            ull n2; ADD2(n2, t2, C_NMAG);           // exact integer-valued n
            ull fr2; FMA2(fr2, n2, C_N1, y2);       // f = y - n
            ull p2 = P5;
            FMA2(p2, p2, fr2, P4);
            FMA2(p2, p2, fr2, P3);
            FMA2(p2, p2, fr2, P2);
            FMA2(p2, p2, fr2, P1);
            FMA2(p2, p2, fr2, P0);
            int t0, t1; upki(t2, t0, t1);
            unsigned e0 = ((unsigned)t0 + 0xB4C0007Fu) << 23;   // (n+127)<<23
            unsigned e1 = ((unsigned)t1 + 0xB4C0007Fu) << 23;
            ull sc2 = pki((int)e0, (int)e1);
            ull e2; MUL2(e2, p2, sc2);
            ADD2(ls2, ls2, e2);
            FMA2(la2, e2, upair[p], la2);
        }
        float2 lsv = upk(ls2), lav = upk(la2);
        float ls = lsv.x + lsv.y;
        float la = lav.x + lav.y;
        ls += __shfl_xor_sync(0xffffffffu, ls, 1);
        la += __shfl_xor_sync(0xffffffffu, la, 1);
        ls += __shfl_xor_sync(0xffffffffu, ls, 2);
        la += __shfl_xor_sync(0xffffffffu, la, 2);

        l_run = fmaf(l_run, corr, ls);
        o_run = fmaf(o_run, corr, la);
        m_run = m_new;
    }

    if (g == 0)
        g_SH[(size_t)abh * SS + q0 + r] = o_run / l_run;
}

// ---------------- combine heads + sigmoid ------------------------------------
__global__ void combine_kernel() {
    int idx = blockIdx.x * blockDim.x + threadIdx.x;   // NA*NB*SS = 16384
    if (idx >= NA * NB * SS) return;
    int q = idx & (SS - 1);
    int ab = idx >> 11;
    float s = 0.f;
#pragma unroll
    for (int h = 0; h < NH; h++) s += g_SH[((size_t)ab * NH + h) * SS + q];
    g_SIG[idx] = 1.0f / (1.0f + expf(-s));
}

// ---------------- sizes (fp64 mean, fp32 final formula, C truncation) --------
__global__ void sizes_kernel(const float* __restrict__ scale_p) {
    int b = blockIdx.x;
    int tid = threadIdx.x;
    __shared__ double red[256];
    double s = 0.0;
    for (int q = tid; q < SS; q += 256) s += (double)g_SIG[b * SS + q];
    red[tid] = s;
    __syncthreads();
    for (int st = 128; st > 0; st >>= 1) {
        if (tid < st) red[tid] += red[tid + st];
        __syncthreads();
    }
    if (tid == 0) {
        float mean = (float)(red[0] / (double)SS);
        float val = mean * scale_p[0] * 8160.0f + 32.0f;
        g_sizes[b] = (int)val;
    }
}

// ---------------- segment weighted pooling + output --------------------------
__global__ __launch_bounds__(256) void pool_kernel(const float* __restrict__ x,
                                                   float* __restrict__ out,
                                                   int ml, int extras) {
    int b = blockIdx.y, j = blockIdx.x, tid = threadIdx.x;
    int sz = g_sizes[b];
    int off = ml - sz;
    float* orow = out + ((size_t)(b * ml + j)) * HID;
    int c = tid * 4;
    size_t maskbase = (size_t)NB * ml * HID;

    if (j < off) {
        *(float4*)&orow[c] = make_float4(0.f, 0.f, 0.f, 0.f);
        if (extras && tid == 0) out[maskbase + (size_t)b * ml + j] = 0.0f;
    } else {
        int s = j - off;
        double step = 2048.0 / (double)sz;
        int lo = (s == 0) ? 0 : (int)floor((double)s * step);
        int hi = (s + 1 == sz) ? SS : (int)floor((double)(s + 1) * step);
        float4 acc = make_float4(0.f, 0.f, 0.f, 0.f);
        float wsum = 0.f;
        const float* wv = g_SIG + (NA - 1) * NB * SS + b * SS;
        const float* xb = x + (size_t)b * SS * HID;
        for (int t = lo; t < hi; t++) {
            float w = wv[t];
            float4 xv = *(const float4*)&xb[(size_t)t * HID + c];
            acc.x = fmaf(xv.x, w, acc.x);
            acc.y = fmaf(xv.y, w, acc.y);
            acc.z = fmaf(xv.z, w, acc.z);
            acc.w = fmaf(xv.w, w, acc.w);
            wsum += w;
        }
        float den = wsum + 1e-8f;
        *(float4*)&orow[c] = make_float4(acc.x / den, acc.y / den, acc.z / den, acc.w / den);
        if (extras && tid == 0) out[maskbase + (size_t)b * ml + j] = 1.0f;
    }
    if (extras && j == 0 && tid == 0)
        out[maskbase + (size_t)NB * ml + b] = (float)sz;
}

// ---------------- host --------------------------------------------------------
extern "C" void kernel_launch(void* const* d_in, const int* in_sizes, int n_in,
                              void* d_out, int out_size) {
    const float* x    = (const float*)d_in[0];
    const float* Wq1  = (const float*)d_in[1];
    const float* Wk1  = (const float*)d_in[2];
    const float* Wv1  = (const float*)d_in[3];
    const float* Wo1  = (const float*)d_in[4];
    const float* Wq2  = (const float*)d_in[5];
    const float* Wk2  = (const float*)d_in[6];
    const float* Wv2  = (const float*)d_in[7];
    const float* Wo2  = (const float*)d_in[8];
    const float* scl  = (const float*)d_in[9];
    float* out = (float*)d_out;

    // derive max_len from out_size: out = B*ml*(HID+1) + B floats
    long long osz = (long long)out_size;
    int ml, extras;
    if (osz > NB && ((osz - NB) % (long long)(NB * (HID + 1))) == 0) {
        ml = (int)((osz - NB) / (NB * (HID + 1)));
        extras = 1;
    } else {
        ml = (int)(osz / (NB * HID));
        extras = 0;
    }
    if (ml < 1) ml = 1;

    pack_weights<<<dim3((NTOT + 255) / 256, HID), 256>>>(Wq1, Wk1, Wv1, Wo1,
                                                         Wq2, Wk2, Wv2, Wo2);
    gemm_fused<<<dim3((NTOT + 127) / 128, (NB * SS) / 128), 256>>>(x);
    ut_kernel<<<(NA * NB * NH * SS + 255) / 256, 256>>>();
    attn_kernel<<<dim3(SS / 64, NA * NB * NH), 256>>>();
    combine_kernel<<<(NA * NB * SS + 255) / 256, 256>>>();
    sizes_kernel<<<NB, 256>>>(scl);
    pool_kernel<<<dim3(ml, NB), 256>>>(x, out, ml, extras);
}

// round 9
// speedup vs baseline: 1.6111x; 1.3186x over previous
#include <cuda_runtime.h>
#include <cuda_bf16.h>
#include <math.h>

// Problem constants
#define NB 4          // batch
#define SS 2048       // seq len
#define HID 1024
#define NH 16         // heads
#define NKV 4
#define DD 64
#define NA 2          // two attentions
#define NTOT 2592     // 1024(Q1)+1024(Q2)+256(K1)+256(K2)+16(U1)+16(U2)
#define QT 128        // queries per CTA (attention)
#define KT 64         // keys per tile (attention)

typedef unsigned long long ull;

// ---------------- scratch (device globals; no allocation allowed) ------------
__device__ float g_Bcat[HID * NTOT];        // concatenated weights [K][NTOT]
__device__ float g_C   [NB * SS * NTOT];    // fused projection output  ~85 MB
__device__ float g_UT  [NA * NB * NH * SS]; // scalar-values transposed (a,b,h,s)
__device__ float g_SH  [NA * NB * NH * SS]; // per-head scalar attention out
__device__ float g_SIG [NA * NB * SS];      // sigmoid(score) per attn
__device__ int   g_sizes[NB];

// ---------------- f32x2 packed helpers ---------------------------------------
__device__ __forceinline__ ull pk(float lo, float hi) {
    ull r; asm("mov.b64 %0, {%1, %2};" : "=l"(r) : "f"(lo), "f"(hi)); return r;
}
__device__ __forceinline__ float2 upk(ull v) {
    float2 r; asm("mov.b64 {%0, %1}, %2;" : "=f"(r.x), "=f"(r.y) : "l"(v)); return r;
}
__device__ __forceinline__ void upki(ull v, int& a, int& b) {
    asm("mov.b64 {%0, %1}, %2;" : "=r"(a), "=r"(b) : "l"(v));
}
__device__ __forceinline__ ull pki(int lo, int hi) {
    ull r; asm("mov.b64 %0, {%1, %2};" : "=l"(r) : "r"(lo), "r"(hi)); return r;
}
#define FMA2(d, a, b, c) asm("fma.rn.f32x2 %0, %1, %2, %3;" : "=l"(d) : "l"(a), "l"(b), "l"(c))
#define MUL2(d, a, b)    asm("mul.rn.f32x2 %0, %1, %2;"     : "=l"(d) : "l"(a), "l"(b))
#define ADD2(d, a, b)    asm("add.rn.f32x2 %0, %1, %2;"     : "=l"(d) : "l"(a), "l"(b))

// packed exp (degree-5 2^f poly, exponent splice; valid for |s| < ~80)
__device__ __forceinline__ ull pexp(ull s2) {
    const ull C_L2E  = pk(1.4426950408889634f, 1.4426950408889634f);
    const ull C_MAG  = pk(12582912.0f, 12582912.0f);
    const ull C_NMAG = pk(-12582912.0f, -12582912.0f);
    const ull C_N1   = pk(-1.0f, -1.0f);
    const ull P5 = pk(1.3333558e-3f, 1.3333558e-3f);
    const ull P4 = pk(9.6181291e-3f, 9.6181291e-3f);
    const ull P3 = pk(5.5504109e-2f, 5.5504109e-2f);
    const ull P2 = pk(2.4022651e-1f, 2.4022651e-1f);
    const ull P1 = pk(6.9314718e-1f, 6.9314718e-1f);
    const ull P0 = pk(1.0f, 1.0f);
    ull y2; MUL2(y2, s2, C_L2E);
    ull t2; ADD2(t2, y2, C_MAG);
    ull n2; ADD2(n2, t2, C_NMAG);
    ull fr2; FMA2(fr2, n2, C_N1, y2);
    ull p2 = P5;
    FMA2(p2, p2, fr2, P4);
    FMA2(p2, p2, fr2, P3);
    FMA2(p2, p2, fr2, P2);
    FMA2(p2, p2, fr2, P1);
    FMA2(p2, p2, fr2, P0);
    int t0, t1; upki(t2, t0, t1);
    unsigned e0 = ((unsigned)t0 + 0xB4C0007Fu) << 23;   // (n+127)<<23
    unsigned e1 = ((unsigned)t1 + 0xB4C0007Fu) << 23;
    ull sc2 = pki((int)e0, (int)e1);
    ull r2; MUL2(r2, p2, sc2);
    return r2;
}

// ---------------- scalar fast exp (FFMA-only, clamped) -----------------------
__device__ __forceinline__ float fexp(float x) {
    x = fmaxf(x, -87.0f);
    float y = x * 1.4426950408889634f;
    float t = y + 12582912.0f;
    int   n = __float_as_int(t) - 0x4B400000;
    float f = y - (t - 12582912.0f);
    float p = 1.3333558e-3f;
    p = fmaf(p, f, 9.6181291e-3f);
    p = fmaf(p, f, 5.5504109e-2f);
    p = fmaf(p, f, 2.4022651e-1f);
    p = fmaf(p, f, 6.9314718e-1f);
    p = fmaf(p, f, 1.0f);
    return p * __int_as_float((n + 127) << 23);
}

// ---------------- weight packing: Bcat[k][c] ---------------------------------
__global__ void pack_weights(const float* __restrict__ Wq1, const float* __restrict__ Wk1,
                             const float* __restrict__ Wv1, const float* __restrict__ Wo1,
                             const float* __restrict__ Wq2, const float* __restrict__ Wk2,
                             const float* __restrict__ Wv2, const float* __restrict__ Wo2) {
    int c = blockIdx.x * 256 + threadIdx.x;
    int k = blockIdx.y;
    if (c >= NTOT) return;
    float v;
    if (c < 1024)      v = Wq1[(size_t)k * 1024 + c];
    else if (c < 2048) v = Wq2[(size_t)k * 1024 + (c - 1024)];
    else if (c < 2304) v = Wk1[(size_t)k * 256 + (c - 2048)];
    else if (c < 2560) v = Wk2[(size_t)k * 256 + (c - 2304)];
    else {
        int cc = c - 2560; int a = cc >> 4, h = cc & 15;
        const float* Wv = a ? Wv2 : Wv1;
        const float* Wo = a ? Wo2 : Wo1;
        int kv = h >> 2;
        float s = 0.f;
        const float* vr = Wv + (size_t)k * (NKV * DD) + kv * DD;
        const float* wr = Wo + h * DD;
#pragma unroll
        for (int d = 0; d < DD; d++) s = fmaf(vr[d], wr[d], s);
        v = s;
    }
    g_Bcat[(size_t)k * NTOT + c] = v;
}

// ---------------- fused projection GEMM: C = x @ Bcat, 128x128x8, f32x2 ------
__global__ __launch_bounds__(256, 2) void gemm_fused(const float* __restrict__ A) {
    __shared__ __align__(16) float As[8][128];
    __shared__ __align__(16) float Bs[8][128];
    const int N = NTOT, K = HID;
    int tid = threadIdx.x;
    int bm = blockIdx.y * 128;
    int bn = blockIdx.x * 128;
    int ty = tid >> 4, tx = tid & 15;

    int arow = tid >> 1, acol = (tid & 1) * 4;
    int brow = tid >> 5, bcol = (tid & 31) * 4;
    int gn = bn + bcol;
    bool edge = (bn + 128 > N);

    ull acc2[8][4];
#pragma unroll
    for (int i = 0; i < 8; i++)
#pragma unroll
        for (int j = 0; j < 4; j++) acc2[i][j] = 0ull;

    const float* Aptr = A + (size_t)(bm + arow) * K + acol;
    const float* Bptr = g_Bcat + (size_t)brow * N + gn;

    float4 apre, bpre;
    apre = *(const float4*)(Aptr);
    if (!edge) bpre = *(const float4*)(Bptr);
    else {
        bpre.x = (gn + 0 < N) ? Bptr[0] : 0.f;
        bpre.y = (gn + 1 < N) ? Bptr[1] : 0.f;
        bpre.z = (gn + 2 < N) ? Bptr[2] : 0.f;
        bpre.w = (gn + 3 < N) ? Bptr[3] : 0.f;
    }

    for (int k0 = 0; k0 < K; k0 += 8) {
        As[acol + 0][arow] = apre.x;
        As[acol + 1][arow] = apre.y;
        As[acol + 2][arow] = apre.z;
        As[acol + 3][arow] = apre.w;
        *(float4*)&Bs[brow][bcol] = bpre;
        __syncthreads();

        if (k0 + 8 < K) {
            apre = *(const float4*)(Aptr + k0 + 8);
            const float* Bp = Bptr + (size_t)(k0 + 8) * N;
            if (!edge) bpre = *(const float4*)Bp;
            else {
                bpre.x = (gn + 0 < N) ? Bp[0] : 0.f;
                bpre.y = (gn + 1 < N) ? Bp[1] : 0.f;
                bpre.z = (gn + 2 < N) ? Bp[2] : 0.f;
                bpre.w = (gn + 3 < N) ? Bp[3] : 0.f;
            }
        }

#pragma unroll
        for (int kk = 0; kk < 8; kk++) {
            float4 a0 = *(const float4*)&As[kk][ty * 4];
            float4 a1 = *(const float4*)&As[kk][64 + ty * 4];
            ulonglong2 b0 = *(const ulonglong2*)&Bs[kk][tx * 4];
            ulonglong2 b1 = *(const ulonglong2*)&Bs[kk][64 + tx * 4];
            ull ap[8];
            ap[0] = pk(a0.x, a0.x); ap[1] = pk(a0.y, a0.y);
            ap[2] = pk(a0.z, a0.z); ap[3] = pk(a0.w, a0.w);
            ap[4] = pk(a1.x, a1.x); ap[5] = pk(a1.y, a1.y);
            ap[6] = pk(a1.z, a1.z); ap[7] = pk(a1.w, a1.w);
            ull bp[4] = {b0.x, b0.y, b1.x, b1.y};
#pragma unroll
            for (int i = 0; i < 8; i++)
#pragma unroll
                for (int j = 0; j < 4; j++) FMA2(acc2[i][j], ap[i], bp[j], acc2[i][j]);
        }
        __syncthreads();
    }

#pragma unroll
    for (int i = 0; i < 8; i++) {
        int row = bm + ((i < 4) ? (ty * 4 + i) : (64 + ty * 4 + i - 4));
#pragma unroll
        for (int j = 0; j < 4; j++) {
            int col = bn + ((j < 2) ? (tx * 4 + j * 2) : (64 + tx * 4 + (j - 2) * 2));
            if (col < N) {
                float2 v = upk(acc2[i][j]);
                *(float2*)&g_C[(size_t)row * N + col] = v;
            }
        }
    }
}

// ---------------- U transpose: C cols -> (a,b,h,s) ---------------------------
__global__ void ut_kernel() {
    int o = blockIdx.x * blockDim.x + threadIdx.x;   // NA*NB*NH*SS = 262144
    if (o >= NA * NB * NH * SS) return;
    int s = o & (SS - 1);
    int abh = o >> 11;
    int h = abh & 15, ab = abh >> 4;
    int a = ab >> 2, b = ab & 3;
    g_UT[o] = g_C[(size_t)(b * SS + s) * NTOT + 2560 + a * 16 + h];
}

// ---------------- attention with scalar values -------------------------------
// grid: (SS/QT, NA*NB*NH), 256 threads. No running max (scores are O(10)),
// register-resident softmax accumulation, Q smem-resident, K streamed.
__global__ __launch_bounds__(256, 2) void attn_kernel() {
    __shared__ __align__(16) float Qs[DD][QT];   // 32 KB, transposed, scaled
    __shared__ __align__(16) float Ks[DD][KT];   // 16 KB, transposed, swizzled

    int tid = threadIdx.x;
    int abh = blockIdx.y;               // (a*NB + b)*NH + h
    int h = abh & 15;
    int ab = abh >> 4;
    int a = ab >> 2, b = ab & 3;
    int q0 = blockIdx.x * QT;

    int qcol = a * 1024 + h * DD;
    int kcol = 2048 + a * 256 + (h >> 2) * DD;
    const float* Cb = g_C + (size_t)b * SS * NTOT;
    const float* UT = g_UT + (size_t)abh * SS;

    // ---- load Q tile transposed + scaled by 1/sqrt(64) ----
    {
        int q = tid >> 1, half = tid & 1;
        const float* src = Cb + (size_t)(q0 + q) * NTOT + qcol + half * 32;
#pragma unroll
        for (int j = 0; j < 8; j++) {
            float4 v = ((const float4*)src)[j];
            int d = half * 32 + j * 4;
            Qs[d + 0][q] = v.x * 0.125f;
            Qs[d + 1][q] = v.y * 0.125f;
            Qs[d + 2][q] = v.z * 0.125f;
            Qs[d + 3][q] = v.w * 0.125f;
        }
    }

    // ---- K prefetch mapping: thread (kk, g4) loads key row kk, d-quarter g4 ----
    int kk = tid >> 2, g4 = tid & 3;
    // swizzled store column (constant per thread): quad (kk>>2)^g4, offset kk&3
    int scol = ((((kk >> 2) ^ g4) << 2) | (kk & 3));

    float4 pre[4];
    {
        const float* src = Cb + (size_t)kk * NTOT + kcol + g4 * 16;
#pragma unroll
        for (int j = 0; j < 4; j++) pre[j] = ((const float4*)src)[j];
    }

    int ty = tid >> 4, tx = tid & 15;   // 16x16 thread grid: 8 rows x 4 cols each

    ull acc2[4][4];                      // [row-pair][col], pairs along rows
    ull lsp[4], lap[4];                  // running denominator / numerator (packed rows)
#pragma unroll
    for (int i = 0; i < 4; i++) { lsp[i] = 0ull; lap[i] = 0ull; }

    for (int kt = 0; kt < SS / KT; kt++) {
        // store prefetched K tile (transposed + swizzled)
#pragma unroll
        for (int j = 0; j < 4; j++) {
            int d = g4 * 16 + j * 4;
            Ks[d + 0][scol] = pre[j].x;
            Ks[d + 1][scol] = pre[j].y;
            Ks[d + 2][scol] = pre[j].z;
            Ks[d + 3][scol] = pre[j].w;
        }
        __syncthreads();

        // prefetch next K tile
        if (kt + 1 < SS / KT) {
            const float* src = Cb + (size_t)((kt + 1) * KT + kk) * NTOT + kcol + g4 * 16;
#pragma unroll
            for (int j = 0; j < 4; j++) pre[j] = ((const float4*)src)[j];
        }

        // ---- scores: 128x64 tile, 8 rows (4 packed pairs) x 4 cols per thread ----
#pragma unroll
        for (int i = 0; i < 4; i++)
#pragma unroll
            for (int j = 0; j < 4; j++) acc2[i][j] = 0ull;

#pragma unroll 16
        for (int d = 0; d < DD; d++) {
            ulonglong2 aq0 = *(const ulonglong2*)&Qs[d][ty * 8];
            ulonglong2 aq1 = *(const ulonglong2*)&Qs[d][ty * 8 + 4];
            const float4 bv = *(const float4*)&Ks[d][((tx ^ ((d >> 4) & 3)) << 2)];
            ull b0 = pk(bv.x, bv.x), b1 = pk(bv.y, bv.y);
            ull b2 = pk(bv.z, bv.z), b3 = pk(bv.w, bv.w);
            ull ap[4] = {aq0.x, aq0.y, aq1.x, aq1.y};
#pragma unroll
            for (int i = 0; i < 4; i++) {
                FMA2(acc2[i][0], ap[i], b0, acc2[i][0]);
                FMA2(acc2[i][1], ap[i], b1, acc2[i][1]);
                FMA2(acc2[i][2], ap[i], b2, acc2[i][2]);
                FMA2(acc2[i][3], ap[i], b3, acc2[i][3]);
            }
        }

        // ---- softmax accumulation (no max subtraction) ----
        const float4 u4 = *(const float4*)(UT + kt * KT + tx * 4);
        ull ud[4] = {pk(u4.x, u4.x), pk(u4.y, u4.y), pk(u4.z, u4.z), pk(u4.w, u4.w)};
#pragma unroll
        for (int i = 0; i < 4; i++) {
#pragma unroll
            for (int j = 0; j < 4; j++) {
                ull e2 = pexp(acc2[i][j]);
                ADD2(lsp[i], lsp[i], e2);
                FMA2(lap[i], e2, ud[j], lap[i]);
            }
        }
        __syncthreads();   // all reads of Ks done before next store
    }

    // ---- final reduce across the 16 tx lanes; rows ty*8 + rp*2 + {0,1} ----
#pragma unroll
    for (int rp = 0; rp < 4; rp++) {
        float2 lsv = upk(lsp[rp]);
        float2 lav = upk(lap[rp]);
        float v0 = lsv.x, v1 = lsv.y, w0 = lav.x, w1 = lav.y;
#pragma unroll
        for (int m = 1; m < 16; m <<= 1) {
            v0 += __shfl_xor_sync(0xffffffffu, v0, m);
            v1 += __shfl_xor_sync(0xffffffffu, v1, m);
            w0 += __shfl_xor_sync(0xffffffffu, w0, m);
            w1 += __shfl_xor_sync(0xffffffffu, w1, m);
        }
        if (tx == 0) {
            int row = q0 + ty * 8 + rp * 2;
            g_SH[(size_t)abh * SS + row + 0] = w0 / v0;
            g_SH[(size_t)abh * SS + row + 1] = w1 / v1;
        }
    }
}

// ---------------- combine heads + sigmoid ------------------------------------
__global__ void combine_kernel() {
    int idx = blockIdx.x * blockDim.x + threadIdx.x;   // NA*NB*SS = 16384
    if (idx >= NA * NB * SS) return;
    int q = idx & (SS - 1);
    int ab = idx >> 11;
    float s = 0.f;
#pragma unroll
    for (int h = 0; h < NH; h++) s += g_SH[((size_t)ab * NH + h) * SS + q];
    g_SIG[idx] = 1.0f / (1.0f + expf(-s));
}

// ---------------- sizes (fp64 mean, fp32 final formula, C truncation) --------
__global__ void sizes_kernel(const float* __restrict__ scale_p) {
    int b = blockIdx.x;
    int tid = threadIdx.x;
    __shared__ double red[256];
    double s = 0.0;
    for (int q = tid; q < SS; q += 256) s += (double)g_SIG[b * SS + q];
    red[tid] = s;
    __syncthreads();
    for (int st = 128; st > 0; st >>= 1) {
        if (tid < st) red[tid] += red[tid + st];
        __syncthreads();
    }
    if (tid == 0) {
        float mean = (float)(red[0] / (double)SS);
        float val = mean * scale_p[0] * 8160.0f + 32.0f;
        g_sizes[b] = (int)val;
    }
}

// ---------------- segment weighted pooling + output --------------------------
__global__ __launch_bounds__(256) void pool_kernel(const float* __restrict__ x,
                                                   float* __restrict__ out,
                                                   int ml, int extras) {
    int b = blockIdx.y, j = blockIdx.x, tid = threadIdx.x;
    int sz = g_sizes[b];
    int off = ml - sz;
    float* orow = out + ((size_t)(b * ml + j)) * HID;
    int c = tid * 4;
    size_t maskbase = (size_t)NB * ml * HID;

    if (j < off) {
        *(float4*)&orow[c] = make_float4(0.f, 0.f, 0.f, 0.f);
        if (extras && tid == 0) out[maskbase + (size_t)b * ml + j] = 0.0f;
    } else {
        int s = j - off;
        double step = 2048.0 / (double)sz;
        int lo = (s == 0) ? 0 : (int)floor((double)s * step);
        int hi = (s + 1 == sz) ? SS : (int)floor((double)(s + 1) * step);
        float4 acc = make_float4(0.f, 0.f, 0.f, 0.f);
        float wsum = 0.f;
        const float* wv = g_SIG + (NA - 1) * NB * SS + b * SS;
        const float* xb = x + (size_t)b * SS * HID;
        for (int t = lo; t < hi; t++) {
            float w = wv[t];
            float4 xv = *(const float4*)&xb[(size_t)t * HID + c];
            acc.x = fmaf(xv.x, w, acc.x);
            acc.y = fmaf(xv.y, w, acc.y);
            acc.z = fmaf(xv.z, w, acc.z);
            acc.w = fmaf(xv.w, w, acc.w);
            wsum += w;
        }
        float den = wsum + 1e-8f;
        *(float4*)&orow[c] = make_float4(acc.x / den, acc.y / den, acc.z / den, acc.w / den);
        if (extras && tid == 0) out[maskbase + (size_t)b * ml + j] = 1.0f;
    }
    if (extras && j == 0 && tid == 0)
        out[maskbase + (size_t)NB * ml + b] = (float)sz;
}

// ---------------- host --------------------------------------------------------
extern "C" void kernel_launch(void* const* d_in, const int* in_sizes, int n_in,
                              void* d_out, int out_size) {
    const float* x    = (const float*)d_in[0];
    const float* Wq1  = (const float*)d_in[1];
    const float* Wk1  = (const float*)d_in[2];
    const float* Wv1  = (const float*)d_in[3];
    const float* Wo1  = (const float*)d_in[4];
    const float* Wq2  = (const float*)d_in[5];
    const float* Wk2  = (const float*)d_in[6];
    const float* Wv2  = (const float*)d_in[7];
    const float* Wo2  = (const float*)d_in[8];
    const float* scl  = (const float*)d_in[9];
    float* out = (float*)d_out;

    // derive max_len from out_size: out = B*ml*(HID+1) + B floats
    long long osz = (long long)out_size;
    int ml, extras;
    if (osz > NB && ((osz - NB) % (long long)(NB * (HID + 1))) == 0) {
        ml = (int)((osz - NB) / (NB * (HID + 1)));
        extras = 1;
    } else {
        ml = (int)(osz / (NB * HID));
        extras = 0;
    }
    if (ml < 1) ml = 1;

    pack_weights<<<dim3((NTOT + 255) / 256, HID), 256>>>(Wq1, Wk1, Wv1, Wo1,
                                                         Wq2, Wk2, Wv2, Wo2);
    gemm_fused<<<dim3((NTOT + 127) / 128, (NB * SS) / 128), 256>>>(x);
    ut_kernel<<<(NA * NB * NH * SS + 255) / 256, 256>>>();
    attn_kernel<<<dim3(SS / QT, NA * NB * NH), 256>>>();
    combine_kernel<<<(NA * NB * SS + 255) / 256, 256>>>();
    sizes_kernel<<<NB, 256>>>(scl);
    pool_kernel<<<dim3(ml, NB), 256>>>(x, out, ml, extras);
}